// round 4
// baseline (speedup 1.0000x reference)
#include <cuda_runtime.h>

// Problem constants (fixed by the reference).
#define N_IN      262144         // INPUT_LAYER
#define HIDDEN    3
#define LAYERS    120
#define NCHAIN    (LAYERS - 1)   // 119
#define OUTPUTS   18

#define BLOCKS    256
#define THREADS   256
// (N_IN/4) / (BLOCKS*THREADS) == 1 : exactly one float4 per thread per W0 row.

#define LOG2E_X2  2.8853900817779268f   // 2/ln(2)

// Scratch (no allocations allowed).
__device__ float    g_part[BLOCKS * 3];   // per-block partial dot products
__device__ unsigned g_count;              // zero at load; reset by block 0
__device__ float4   g_H[LAYERS];          // stacked hidden states (xyz used)

// tanh from PRE-SCALED argument t = 2x/ln2:
//   e = 2^t = e^{2x};  tanh = 1 - 2/(e+1).
// Saturation-safe: e=inf -> 1; e=0 -> -1. Chain EX2+FADD+RCP+FMA ~= 40cyc.
__device__ __forceinline__ float tanh_scaled(float t) {
    float e, r;
    asm("ex2.approx.f32 %0, %1;" : "=f"(e) : "f"(t));
    float den = e + 1.0f;
    asm("rcp.approx.f32 %0, %1;" : "=f"(r) : "f"(den));
    return fmaf(-2.0f, r, 1.0f);
}

__global__ __launch_bounds__(THREADS, 1)
void dqn_fused_kernel(const float* __restrict__ x,
                      const float* __restrict__ W0,     // (3, 262144)
                      const float* __restrict__ bih0,   // (3,)
                      const float* __restrict__ bhh0,   // (3,)
                      const float* __restrict__ Wl,     // (119, 3, 3)
                      const float* __restrict__ bil,    // (119, 3)
                      const float* __restrict__ bhl,    // (119, 3)
                      const float* __restrict__ Wh,     // (18, 120)
                      const float* __restrict__ bh,     // (18,)
                      float* __restrict__ out)          // (3, 18)
{
    __shared__ float wsum[3][8];

    const int tid = threadIdx.x;
    const int g   = blockIdx.x * THREADS + tid;

    // ---------------- Phase 1: partial dot products (HBM burst) -------------
    const float4 xv = reinterpret_cast<const float4*>(x)[g];
    const float4 a0 = reinterpret_cast<const float4*>(W0)[g];
    const float4 a1 = reinterpret_cast<const float4*>(W0 + N_IN)[g];
    const float4 a2 = reinterpret_cast<const float4*>(W0 + 2 * N_IN)[g];

    float s0 = a0.x * xv.x + a0.y * xv.y + a0.z * xv.z + a0.w * xv.w;
    float s1 = a1.x * xv.x + a1.y * xv.y + a1.z * xv.z + a1.w * xv.w;
    float s2 = a2.x * xv.x + a2.y * xv.y + a2.z * xv.z + a2.w * xv.w;

    #pragma unroll
    for (int off = 16; off > 0; off >>= 1) {
        s0 += __shfl_down_sync(0xFFFFFFFFu, s0, off);
        s1 += __shfl_down_sync(0xFFFFFFFFu, s1, off);
        s2 += __shfl_down_sync(0xFFFFFFFFu, s2, off);
    }
    const int wid = tid >> 5, lid = tid & 31;
    if (lid == 0) { wsum[0][wid] = s0; wsum[1][wid] = s1; wsum[2][wid] = s2; }
    __syncthreads();

    // ---------------- Non-tail blocks: publish partial and exit -------------
    if (blockIdx.x != 0) {
        if (tid == 0) {
            float b0 = 0.f, b1 = 0.f, b2 = 0.f;
            #pragma unroll
            for (int w = 0; w < 8; ++w) {
                b0 += wsum[0][w]; b1 += wsum[1][w]; b2 += wsum[2][w];
            }
            __stcg(&g_part[blockIdx.x * 3 + 0], b0);
            __stcg(&g_part[blockIdx.x * 3 + 1], b1);
            __stcg(&g_part[blockIdx.x * 3 + 2], b2);
            __threadfence();                 // release partials
            atomicAdd(&g_count, 1u);
        }
        return;
    }

    // ======================= Block 0: tail block =============================
    // Chain weights packed 12 floats/layer (9 W + 3 fused bias), pre-scaled by
    // 2/ln2 so each layer's tanh skips its leading FMUL. One pad layer so the
    // software-pipeline prefetch of layer l+1 never reads OOB.
    __shared__ float4 sP[(NCHAIN + 1) * 3];
    __shared__ float  sWh[OUTPUTS * LAYERS];

    float bias00 = 0.f, bias01 = 0.f, bias02 = 0.f;   // layer-0 fused biases

    if (tid == 0) {
        float b0 = 0.f, b1 = 0.f, b2 = 0.f;
        #pragma unroll
        for (int w = 0; w < 8; ++w) {
            b0 += wsum[0][w]; b1 += wsum[1][w]; b2 += wsum[2][w];
        }
        __stcg(&g_part[0], b0);
        __stcg(&g_part[1], b1);
        __stcg(&g_part[2], b2);
        // Prefetch layer-0 biases while producers are still running.
        bias00 = bih0[0] + bhh0[0];
        bias01 = bih0[1] + bhh0[1];
        bias02 = bih0[2] + bhh0[2];
    }

    // Cooperative preload + repack + pre-scale (overlaps producers' phase 1).
    float* sPf = reinterpret_cast<float*>(sP);
    for (int i = tid; i < NCHAIN * 12; i += THREADS) {
        const int l = i / 12, k = i - l * 12;
        const float v = (k < 9) ? Wl[l * 9 + k]
                                : bil[l * 3 + (k - 9)] + bhl[l * 3 + (k - 9)];
        sPf[i] = v * LOG2E_X2;
    }
    for (int i = tid; i < OUTPUTS * LAYERS; i += THREADS) sWh[i] = Wh[i];

    // Wait for all 255 producer blocks (acquire), then reset the counter.
    if (tid == 0) {
        unsigned v;
        do {
            asm volatile("ld.global.acquire.gpu.u32 %0, [%1];"
                         : "=r"(v) : "l"(&g_count));
        } while (v < BLOCKS - 1);
        g_count = 0;                         // ready for next graph replay
    }
    __syncthreads();   // sP/sWh visible; partials globally visible (via tid0)

    // Warp 0: gather 256 partials (fixed order -> deterministic) and
    // shuffle-reduce so LANE 0 ends with the totals in registers.
    float r0 = 0.f, r1 = 0.f, r2 = 0.f;
    if (tid < 32) {
        const int base = tid * 8;
        #pragma unroll
        for (int k = 0; k < 8; ++k) {
            r0 += __ldcg(&g_part[(base + k) * 3 + 0]);
            r1 += __ldcg(&g_part[(base + k) * 3 + 1]);
            r2 += __ldcg(&g_part[(base + k) * 3 + 2]);
        }
        #pragma unroll
        for (int off = 16; off > 0; off >>= 1) {
            r0 += __shfl_down_sync(0xFFFFFFFFu, r0, off);
            r1 += __shfl_down_sync(0xFFFFFFFFu, r1, off);
            r2 += __shfl_down_sync(0xFFFFFFFFu, r2, off);
        }
    }

    // ---------------- Phase 2: serial 119-layer chain (1 thread) ------------
    // Hidden states go to GLOBAL memory (g_H): STG cannot alias the shared
    // weight loads, so ptxas is free to hoist next-layer LDS.128 prefetches
    // across iterations and the LDS latency hides under the tanh chain.
    if (tid == 0) {
        float h0 = tanh_scaled((r0 + bias00) * LOG2E_X2);
        float h1 = tanh_scaled((r1 + bias01) * LOG2E_X2);
        float h2 = tanh_scaled((r2 + bias02) * LOG2E_X2);
        g_H[0] = make_float4(h0, h1, h2, 0.f);

        float4 c0 = sP[0], c1 = sP[1], c2 = sP[2];
        #pragma unroll
        for (int l = 0; l < NCHAIN; ++l) {
            const float4 n0 = sP[(l + 1) * 3 + 0];
            const float4 n1 = sP[(l + 1) * 3 + 1];
            const float4 n2 = sP[(l + 1) * 3 + 2];
            // layout: w = {c0.x..c0.w, c1.x..c1.w, c2.x}, b = {c2.y,c2.z,c2.w}
            // (all pre-scaled by 2/ln2)
            const float t0 = fmaf(c0.x, h0, fmaf(c0.y, h1, fmaf(c0.z, h2, c2.y)));
            const float t1 = fmaf(c0.w, h0, fmaf(c1.x, h1, fmaf(c1.y, h2, c2.z)));
            const float t2 = fmaf(c1.z, h0, fmaf(c1.w, h1, fmaf(c2.x, h2, c2.w)));
            h0 = tanh_scaled(t0);
            h1 = tanh_scaled(t1);
            h2 = tanh_scaled(t2);
            g_H[l + 1] = make_float4(h0, h1, h2, 0.f);
            c0 = n0; c1 = n1; c2 = n2;
        }
    }
    __syncthreads();   // orders tid0's g_H stores before other threads' loads

    // ---------------- Phase 3: head (54 parallel dot products) --------------
    if (tid < HIDDEN * OUTPUTS) {
        const int j = tid / OUTPUTS;     // hidden index 0..2
        const int o = tid % OUTPUTS;     // output index 0..17
        float acc = bh[o];
        const float* whrow = &sWh[o * LAYERS];
        #pragma unroll 8
        for (int l = 0; l < LAYERS; ++l) {
            const float4 hv = g_H[l];
            const float  hj = (j == 0) ? hv.x : ((j == 1) ? hv.y : hv.z);
            acc = fmaf(hj, whrow[l], acc);
        }
        out[j * OUTPUTS + o] = acc;      // row-major (3, 18)
    }
}

extern "C" void kernel_launch(void* const* d_in, const int* in_sizes, int n_in,
                              void* d_out, int out_size) {
    const float* x    = (const float*)d_in[0];
    const float* W0   = (const float*)d_in[1];
    const float* bih0 = (const float*)d_in[2];
    const float* bhh0 = (const float*)d_in[3];
    const float* Wl   = (const float*)d_in[4];
    const float* bil  = (const float*)d_in[5];
    const float* bhl  = (const float*)d_in[6];
    const float* Wh   = (const float*)d_in[7];
    const float* bh   = (const float*)d_in[8];
    float* out        = (float*)d_out;

    dqn_fused_kernel<<<BLOCKS, THREADS>>>(x, W0, bih0, bhh0,
                                          Wl, bil, bhl, Wh, bh, out);
}

// round 5
// speedup vs baseline: 1.4575x; 1.4575x over previous
#include <cuda_runtime.h>

// Problem constants (fixed by the reference).
#define N_IN      262144         // INPUT_LAYER
#define HIDDEN    3
#define LAYERS    120
#define NCHAIN    (LAYERS - 1)   // 119
#define OUTPUTS   18

#define BLOCKS    256
#define THREADS   256
// (N_IN/4) / (BLOCKS*THREADS) == 1 : exactly one float4 per thread per W0 row.

#define LOG2E_X2  2.8853900817779268f   // 2/ln(2)

// Scratch (no allocations allowed).
__device__ float    g_part[BLOCKS * 3];   // per-block partial dot products
__device__ unsigned g_count;              // zero at load; reset by block 0
__device__ float4   g_H[LAYERS];          // stacked hidden states (xyz used)

// tanh from PRE-SCALED argument t = 2x/ln2:
//   e = 2^t = e^{2x};  tanh = 1 - 2/(e+1).
// Saturation-safe: e=inf -> 1; e=0 -> -1. Chain EX2+FADD+RCP+FMA ~= 40cyc.
__device__ __forceinline__ float tanh_scaled(float t) {
    float e, r;
    asm("ex2.approx.f32 %0, %1;" : "=f"(e) : "f"(t));
    float den = e + 1.0f;
    asm("rcp.approx.f32 %0, %1;" : "=f"(r) : "f"(den));
    return fmaf(-2.0f, r, 1.0f);
}

__global__ __launch_bounds__(THREADS)
void dqn_fused_kernel(const float* __restrict__ x,
                      const float* __restrict__ W0,     // (3, 262144)
                      const float* __restrict__ bih0,   // (3,)
                      const float* __restrict__ bhh0,   // (3,)
                      const float* __restrict__ Wl,     // (119, 3, 3)
                      const float* __restrict__ bil,    // (119, 3)
                      const float* __restrict__ bhl,    // (119, 3)
                      const float* __restrict__ Wh,     // (18, 120)
                      const float* __restrict__ bh,     // (18,)
                      float* __restrict__ out)          // (3, 18)
{
    __shared__ float wsum[3][8];

    const int tid = threadIdx.x;
    const int g   = blockIdx.x * THREADS + tid;

    // ---------------- Phase 1: partial dot products (HBM burst) -------------
    const float4 xv = reinterpret_cast<const float4*>(x)[g];
    const float4 a0 = reinterpret_cast<const float4*>(W0)[g];
    const float4 a1 = reinterpret_cast<const float4*>(W0 + N_IN)[g];
    const float4 a2 = reinterpret_cast<const float4*>(W0 + 2 * N_IN)[g];

    float s0 = a0.x * xv.x + a0.y * xv.y + a0.z * xv.z + a0.w * xv.w;
    float s1 = a1.x * xv.x + a1.y * xv.y + a1.z * xv.z + a1.w * xv.w;
    float s2 = a2.x * xv.x + a2.y * xv.y + a2.z * xv.z + a2.w * xv.w;

    #pragma unroll
    for (int off = 16; off > 0; off >>= 1) {
        s0 += __shfl_down_sync(0xFFFFFFFFu, s0, off);
        s1 += __shfl_down_sync(0xFFFFFFFFu, s1, off);
        s2 += __shfl_down_sync(0xFFFFFFFFu, s2, off);
    }
    const int wid = tid >> 5, lid = tid & 31;
    if (lid == 0) { wsum[0][wid] = s0; wsum[1][wid] = s1; wsum[2][wid] = s2; }
    __syncthreads();

    // ---------------- Non-tail blocks: publish partial and exit -------------
    if (blockIdx.x != 0) {
        if (tid == 0) {
            float b0 = 0.f, b1 = 0.f, b2 = 0.f;
            #pragma unroll
            for (int w = 0; w < 8; ++w) {
                b0 += wsum[0][w]; b1 += wsum[1][w]; b2 += wsum[2][w];
            }
            __stcg(&g_part[blockIdx.x * 3 + 0], b0);
            __stcg(&g_part[blockIdx.x * 3 + 1], b1);
            __stcg(&g_part[blockIdx.x * 3 + 2], b2);
            __threadfence();                 // release partials
            atomicAdd(&g_count, 1u);
        }
        return;
    }

    // ======================= Block 0: tail block =============================
    // Chain weights packed 12 floats/layer (9 W + 3 fused bias), pre-scaled by
    // 2/ln2 so each layer's tanh skips its leading FMUL. One pad layer so the
    // software-pipeline prefetch of layer l+1 never reads OOB.
    __shared__ float4 sP[(NCHAIN + 1) * 3];
    __shared__ float  sWh[OUTPUTS * LAYERS];
    __shared__ float  sBh[OUTPUTS];
    __shared__ float  sHH[LAYERS * 3];       // hidden states for the head

    float bias00 = 0.f, bias01 = 0.f, bias02 = 0.f;   // layer-0 fused biases

    if (tid == 0) {
        float b0 = 0.f, b1 = 0.f, b2 = 0.f;
        #pragma unroll
        for (int w = 0; w < 8; ++w) {
            b0 += wsum[0][w]; b1 += wsum[1][w]; b2 += wsum[2][w];
        }
        __stcg(&g_part[0], b0);
        __stcg(&g_part[1], b1);
        __stcg(&g_part[2], b2);
        // Prefetch layer-0 biases while producers are still running.
        bias00 = bih0[0] + bhh0[0];
        bias01 = bih0[1] + bhh0[1];
        bias02 = bih0[2] + bhh0[2];
    }

    // Cooperative preload + repack + pre-scale (overlaps producers' phase 1).
    float* sPf = reinterpret_cast<float*>(sP);
    for (int i = tid; i < NCHAIN * 12; i += THREADS) {
        const int l = i / 12, k = i - l * 12;
        const float v = (k < 9) ? Wl[l * 9 + k]
                                : bil[l * 3 + (k - 9)] + bhl[l * 3 + (k - 9)];
        sPf[i] = v * LOG2E_X2;
    }
    for (int i = tid; i < OUTPUTS * LAYERS; i += THREADS) sWh[i] = Wh[i];
    if (tid < OUTPUTS) sBh[tid] = bh[tid];

    // Wait for all 255 producer blocks (acquire), then reset the counter.
    if (tid == 0) {
        unsigned v;
        do {
            asm volatile("ld.global.acquire.gpu.u32 %0, [%1];"
                         : "=r"(v) : "l"(&g_count));
        } while (v < BLOCKS - 1);
        g_count = 0;                         // ready for next graph replay
    }
    __syncthreads();   // sP/sWh/sBh visible; partials globally visible

    // Warp 0: gather 256 partials (fixed order -> deterministic) and
    // shuffle-reduce so LANE 0 ends with the totals in registers.
    float r0 = 0.f, r1 = 0.f, r2 = 0.f;
    if (tid < 32) {
        const int base = tid * 8;
        #pragma unroll
        for (int k = 0; k < 8; ++k) {
            r0 += __ldcg(&g_part[(base + k) * 3 + 0]);
            r1 += __ldcg(&g_part[(base + k) * 3 + 1]);
            r2 += __ldcg(&g_part[(base + k) * 3 + 2]);
        }
        #pragma unroll
        for (int off = 16; off > 0; off >>= 1) {
            r0 += __shfl_down_sync(0xFFFFFFFFu, r0, off);
            r1 += __shfl_down_sync(0xFFFFFFFFu, r1, off);
            r2 += __shfl_down_sync(0xFFFFFFFFu, r2, off);
        }
    }

    // ---------------- Phase 2: serial 119-layer chain (1 thread) ------------
    // Hidden states go to GLOBAL (g_H): STG cannot alias the shared weight
    // loads, so the explicit next-layer LDS.128 prefetch is hoistable and its
    // latency hides under the tanh chain. Bounded unroll keeps the body in
    // registers and the L0 I-cache (the full unroll blew both: regs=255).
    if (tid == 0) {
        float h0 = tanh_scaled((r0 + bias00) * LOG2E_X2);
        float h1 = tanh_scaled((r1 + bias01) * LOG2E_X2);
        float h2 = tanh_scaled((r2 + bias02) * LOG2E_X2);
        g_H[0] = make_float4(h0, h1, h2, 0.f);

        float4 c0 = sP[0], c1 = sP[1], c2 = sP[2];
        #pragma unroll 7
        for (int l = 0; l < NCHAIN; ++l) {
            const float4 n0 = sP[(l + 1) * 3 + 0];
            const float4 n1 = sP[(l + 1) * 3 + 1];
            const float4 n2 = sP[(l + 1) * 3 + 2];
            // layout: w = {c0.x..c0.w, c1.x..c1.w, c2.x}, b = {c2.y,c2.z,c2.w}
            // (all pre-scaled by 2/ln2)
            const float t0 = fmaf(c0.x, h0, fmaf(c0.y, h1, fmaf(c0.z, h2, c2.y)));
            const float t1 = fmaf(c0.w, h0, fmaf(c1.x, h1, fmaf(c1.y, h2, c2.z)));
            const float t2 = fmaf(c1.z, h0, fmaf(c1.w, h1, fmaf(c2.x, h2, c2.w)));
            h0 = tanh_scaled(t0);
            h1 = tanh_scaled(t1);
            h2 = tanh_scaled(t2);
            g_H[l + 1] = make_float4(h0, h1, h2, 0.f);
            c0 = n0; c1 = n1; c2 = n2;
        }
    }
    __syncthreads();   // orders tid0's g_H stores before other threads' loads

    // Copy hidden states (L1/L2-hot) into shared once; head reads LDS.
    if (tid < LAYERS) {
        const float4 hv = g_H[tid];
        sHH[tid * 3 + 0] = hv.x;
        sHH[tid * 3 + 1] = hv.y;
        sHH[tid * 3 + 2] = hv.z;
    }
    __syncthreads();

    // ---------------- Phase 3: head (54 parallel dot products) --------------
    if (tid < HIDDEN * OUTPUTS) {
        const int j = tid / OUTPUTS;     // hidden index 0..2
        const int o = tid % OUTPUTS;     // output index 0..17
        float acc = sBh[o];
        const float* whrow = &sWh[o * LAYERS];
        #pragma unroll 8
        for (int l = 0; l < LAYERS; ++l)
            acc = fmaf(sHH[l * 3 + j], whrow[l], acc);
        out[j * OUTPUTS + o] = acc;      // row-major (3, 18)
    }
}

extern "C" void kernel_launch(void* const* d_in, const int* in_sizes, int n_in,
                              void* d_out, int out_size) {
    const float* x    = (const float*)d_in[0];
    const float* W0   = (const float*)d_in[1];
    const float* bih0 = (const float*)d_in[2];
    const float* bhh0 = (const float*)d_in[3];
    const float* Wl   = (const float*)d_in[4];
    const float* bil  = (const float*)d_in[5];
    const float* bhl  = (const float*)d_in[6];
    const float* Wh   = (const float*)d_in[7];
    const float* bh   = (const float*)d_in[8];
    float* out        = (float*)d_out;

    dqn_fused_kernel<<<BLOCKS, THREADS>>>(x, W0, bih0, bhh0,
                                          Wl, bil, bhl, Wh, bh, out);
}